// round 1
// baseline (speedup 1.0000x reference)
#include <cuda_runtime.h>
#include <math.h>

// Problem dims (fixed by the reference)
#define B_ 8
#define T_ 2048
#define C_ 1024
#define F_ 4096
#define M_ (B_ * T_)   // 16384 rows

constexpr size_t S_  = (size_t)M_ * C_;   // 16,777,216
constexpr size_t SF_ = (size_t)M_ * F_;   // 67,108,864

// ---------------------------------------------------------------------------
// Scratch (static device globals — allocation-free per harness rules)
// ---------------------------------------------------------------------------
__device__ float g_h[S_];
__device__ float g_xk[S_];
__device__ float g_xv[S_];
__device__ float g_xr[S_];
__device__ float g_k[S_];
__device__ float g_v[S_];
__device__ float g_r[S_];
__device__ float g_rwkv[S_];
__device__ float g_short[S_];
__device__ float g_x2[S_];
__device__ float g_g[S_];
__device__ float g_gk[S_];
__device__ float g_gr[S_];
__device__ float g_kv[S_];
__device__ float g_kk[SF_];

// ---------------------------------------------------------------------------
// LayerNorm over last dim (C=1024). One block (256 thr) per row; each thread
// owns one float4.
// ---------------------------------------------------------------------------
__global__ void __launch_bounds__(256) ln_kernel(const float* __restrict__ x,
                                                 const float* __restrict__ w,
                                                 const float* __restrict__ b,
                                                 float* __restrict__ out) {
    const size_t row = blockIdx.x;
    const float4* xr = (const float4*)(x + row * C_);
    const int tid = threadIdx.x;

    float4 xv = xr[tid];
    float s  = xv.x + xv.y + xv.z + xv.w;
    float ss = xv.x * xv.x + xv.y * xv.y + xv.z * xv.z + xv.w * xv.w;

    // warp reduce
    #pragma unroll
    for (int o = 16; o > 0; o >>= 1) {
        s  += __shfl_down_sync(0xffffffffu, s,  o);
        ss += __shfl_down_sync(0xffffffffu, ss, o);
    }
    __shared__ float sm_s[8], sm_ss[8];
    int wid = tid >> 5, lid = tid & 31;
    if (lid == 0) { sm_s[wid] = s; sm_ss[wid] = ss; }
    __syncthreads();
    if (wid == 0) {
        s  = (lid < 8) ? sm_s[lid]  : 0.f;
        ss = (lid < 8) ? sm_ss[lid] : 0.f;
        #pragma unroll
        for (int o = 4; o > 0; o >>= 1) {
            s  += __shfl_down_sync(0xffffffffu, s,  o);
            ss += __shfl_down_sync(0xffffffffu, ss, o);
        }
        if (lid == 0) { sm_s[0] = s; sm_ss[0] = ss; }
    }
    __syncthreads();
    const float mean = sm_s[0] * (1.0f / C_);
    const float var  = sm_ss[0] * (1.0f / C_) - mean * mean;
    const float rstd = rsqrtf(var + 1e-5f);

    float4 wv = ((const float4*)w)[tid];
    float4 bv = ((const float4*)b)[tid];
    float4 ov;
    ov.x = (xv.x - mean) * rstd * wv.x + bv.x;
    ov.y = (xv.y - mean) * rstd * wv.y + bv.y;
    ov.z = (xv.z - mean) * rstd * wv.z + bv.z;
    ov.w = (xv.w - mean) * rstd * wv.w + bv.w;
    ((float4*)(out + row * C_))[tid] = ov;
}

// ---------------------------------------------------------------------------
// Time-shift + mix (3 outputs for attention, 2 for ffn)
// ---------------------------------------------------------------------------
__global__ void __launch_bounds__(256) mix3_kernel(const float* __restrict__ h,
                                                   const float* __restrict__ mk,
                                                   const float* __restrict__ mv,
                                                   const float* __restrict__ mr,
                                                   float* __restrict__ xk,
                                                   float* __restrict__ xv,
                                                   float* __restrict__ xr) {
    size_t idx = (size_t)blockIdx.x * blockDim.x + threadIdx.x;
    if (idx >= S_) return;
    const int c = (int)(idx & (C_ - 1));
    const size_t row = idx >> 10;         // C_=1024
    const int t = (int)(row & (T_ - 1));
    float hc = h[idx];
    float hh = (t == 0) ? 0.f : h[idx - C_];
    float a;
    a = mk[c]; xk[idx] = hc * a + hh * (1.f - a);
    a = mv[c]; xv[idx] = hc * a + hh * (1.f - a);
    a = mr[c]; xr[idx] = hc * a + hh * (1.f - a);
}

__global__ void __launch_bounds__(256) mix2_kernel(const float* __restrict__ h,
                                                   const float* __restrict__ mk,
                                                   const float* __restrict__ mr,
                                                   float* __restrict__ xk,
                                                   float* __restrict__ xr) {
    size_t idx = (size_t)blockIdx.x * blockDim.x + threadIdx.x;
    if (idx >= S_) return;
    const int c = (int)(idx & (C_ - 1));
    const size_t row = idx >> 10;
    const int t = (int)(row & (T_ - 1));
    float hc = h[idx];
    float hh = (t == 0) ? 0.f : h[idx - C_];
    float a;
    a = mk[c]; xk[idx] = hc * a + hh * (1.f - a);
    a = mr[c]; xr[idx] = hc * a + hh * (1.f - a);
}

// ---------------------------------------------------------------------------
// WKV recurrence: one thread per (b, c) channel, sequential over T.
// Fuses the sigmoid(r) gate: out = sigmoid_r * y.
// ---------------------------------------------------------------------------
__global__ void __launch_bounds__(256) wkv_kernel(const float* __restrict__ decay,
                                                  const float* __restrict__ first,
                                                  const float* __restrict__ k,
                                                  const float* __restrict__ v,
                                                  const float* __restrict__ r,
                                                  float* __restrict__ out) {
    int gid = blockIdx.x * blockDim.x + threadIdx.x;   // 0 .. B_*C_-1
    if (gid >= B_ * C_) return;
    const int b = gid / C_;
    const int c = gid - b * C_;
    const float w = -__expf(decay[c]);
    const float u = first[c];
    size_t off = (size_t)b * T_ * C_ + c;

    float a = 0.f, bb = 0.f, p = -1e30f;
    for (int t = 0; t < T_; ++t, off += C_) {
        const float kt = k[off];
        const float vt = v[off];
        const float ww = u + kt;
        const float q  = fmaxf(p, ww);
        const float e1 = __expf(p - q);
        const float e2 = __expf(ww - q);
        const float y  = (e1 * a + e2 * vt) / (e1 * bb + e2);
        out[off] = y * r[off];
        const float ww2 = p + w;
        const float q2  = fmaxf(ww2, kt);
        const float f1  = __expf(ww2 - q2);
        const float f2  = __expf(kt - q2);
        a  = f1 * a + f2 * vt;
        bb = f1 * bb + f2;
        p  = q2;
    }
}

// ---------------------------------------------------------------------------
// SGEMM  C[M,N] = A[M,K] * W[N,K]^T   (both K-contiguous)
// 128x128 tile, BK=8, 256 threads, 8x8 per thread, fused epilogues.
// MODE: 0 = store, 1 = sigmoid, 2 = relu^2, 3 = +aux1,
//       4 = aux1 + sigmoid(acc)*aux2
// ---------------------------------------------------------------------------
template <int MODE>
__global__ void __launch_bounds__(256) gemm_nt(const float* __restrict__ A,
                                               const float* __restrict__ W,
                                               float* __restrict__ C,
                                               const float* __restrict__ aux1,
                                               const float* __restrict__ aux2,
                                               int M, int N, int K) {
    __shared__ float As[8][128];
    __shared__ float Bs[8][128];

    const int tid  = threadIdx.x;
    const int brow = blockIdx.y;
    const int bcol = blockIdx.x;

    const float* Ab = A + (size_t)brow * 128 * K;
    const float* Wb = W + (size_t)bcol * 128 * K;

    const int lr = tid >> 1;           // 0..127
    const int lc = (tid & 1) * 4;      // 0 or 4
    const int ty = tid >> 4;           // 0..15
    const int tx = tid & 15;           // 0..15

    float acc[8][8];
    #pragma unroll
    for (int i = 0; i < 8; ++i)
        #pragma unroll
        for (int j = 0; j < 8; ++j) acc[i][j] = 0.f;

    for (int k0 = 0; k0 < K; k0 += 8) {
        float4 a4 = *(const float4*)(Ab + (size_t)lr * K + k0 + lc);
        float4 b4 = *(const float4*)(Wb + (size_t)lr * K + k0 + lc);
        As[lc + 0][lr] = a4.x; As[lc + 1][lr] = a4.y;
        As[lc + 2][lr] = a4.z; As[lc + 3][lr] = a4.w;
        Bs[lc + 0][lr] = b4.x; Bs[lc + 1][lr] = b4.y;
        Bs[lc + 2][lr] = b4.z; Bs[lc + 3][lr] = b4.w;
        __syncthreads();

        #pragma unroll
        for (int kk = 0; kk < 8; ++kk) {
            float4 a0 = *(const float4*)&As[kk][ty * 8];
            float4 a1 = *(const float4*)&As[kk][ty * 8 + 4];
            float4 b0 = *(const float4*)&Bs[kk][tx * 8];
            float4 b1 = *(const float4*)&Bs[kk][tx * 8 + 4];
            float av[8] = {a0.x, a0.y, a0.z, a0.w, a1.x, a1.y, a1.z, a1.w};
            float bv[8] = {b0.x, b0.y, b0.z, b0.w, b1.x, b1.y, b1.z, b1.w};
            #pragma unroll
            for (int i = 0; i < 8; ++i)
                #pragma unroll
                for (int j = 0; j < 8; ++j)
                    acc[i][j] = fmaf(av[i], bv[j], acc[i][j]);
        }
        __syncthreads();
    }

    #pragma unroll
    for (int i = 0; i < 8; ++i) {
        const int row = brow * 128 + ty * 8 + i;
        size_t roff = (size_t)row * N + bcol * 128 + tx * 8;
        #pragma unroll
        for (int j = 0; j < 8; ++j) {
            float val = acc[i][j];
            if (MODE == 1) {
                val = 1.f / (1.f + __expf(-val));
            } else if (MODE == 2) {
                val = fmaxf(val, 0.f);
                val = val * val;
            } else if (MODE == 3) {
                val += aux1[roff + j];
            } else if (MODE == 4) {
                float sg = 1.f / (1.f + __expf(-val));
                val = aux1[roff + j] + sg * aux2[roff + j];
            }
            C[roff + j] = val;
        }
    }
}

// ---------------------------------------------------------------------------
// Launch
// ---------------------------------------------------------------------------
static float* sym(const void* s) {
    void* p = nullptr;
    cudaGetSymbolAddress(&p, s);
    return (float*)p;
}

extern "C" void kernel_launch(void* const* d_in, const int* in_sizes, int n_in,
                              void* d_out, int out_size) {
    const float* x        = (const float*)d_in[0];
    const float* ln1_w    = (const float*)d_in[1];
    const float* ln1_b    = (const float*)d_in[2];
    const float* ln2_w    = (const float*)d_in[3];
    const float* ln2_b    = (const float*)d_in[4];
    const float* t_decay  = (const float*)d_in[5];
    const float* t_first  = (const float*)d_in[6];
    const float* mix_k    = (const float*)d_in[7];
    const float* mix_v    = (const float*)d_in[8];
    const float* mix_r    = (const float*)d_in[9];
    const float* Wk       = (const float*)d_in[10];
    const float* Wv       = (const float*)d_in[11];
    const float* Wr       = (const float*)d_in[12];
    const float* Wo       = (const float*)d_in[13];
    const float* fmix_k   = (const float*)d_in[14];
    const float* fmix_r   = (const float*)d_in[15];
    const float* fWk      = (const float*)d_in[16];   // [F, C]
    const float* fWr      = (const float*)d_in[17];   // [C, C]
    const float* fWv      = (const float*)d_in[18];   // [C, F]
    const float* shortW   = (const float*)d_in[19];
    float* out = (float*)d_out;

    float* h     = sym(g_h);
    float* xk    = sym(g_xk);
    float* xv    = sym(g_xv);
    float* xr    = sym(g_xr);
    float* kbuf  = sym(g_k);
    float* vbuf  = sym(g_v);
    float* rbuf  = sym(g_r);
    float* rwkv  = sym(g_rwkv);
    float* shrt  = sym(g_short);
    float* x2    = sym(g_x2);
    float* gbuf  = sym(g_g);
    float* gk    = sym(g_gk);
    float* gr    = sym(g_gr);
    float* kvb   = sym(g_kv);
    float* kkb   = sym(g_kk);

    const dim3 blk(256);
    const dim3 grid_elem((unsigned)((S_ + 255) / 256));
    const dim3 grid_gC(C_ / 128, M_ / 128);   // N=1024
    const dim3 grid_gF(F_ / 128, M_ / 128);   // N=4096

    // --- TimeMix path ---
    ln_kernel<<<M_, blk>>>(x, ln1_w, ln1_b, h);
    mix3_kernel<<<grid_elem, blk>>>(h, mix_k, mix_v, mix_r, xk, xv, xr);
    gemm_nt<0><<<grid_gC, blk>>>(xk, Wk, kbuf, nullptr, nullptr, M_, C_, C_);
    gemm_nt<0><<<grid_gC, blk>>>(xv, Wv, vbuf, nullptr, nullptr, M_, C_, C_);
    gemm_nt<1><<<grid_gC, blk>>>(xr, Wr, rbuf, nullptr, nullptr, M_, C_, C_);
    wkv_kernel<<<(B_ * C_) / 256, blk>>>(t_decay, t_first, kbuf, vbuf, rbuf, rwkv);
    gemm_nt<0><<<grid_gC, blk>>>(x, shortW, shrt, nullptr, nullptr, M_, C_, C_);
    gemm_nt<3><<<grid_gC, blk>>>(rwkv, Wo, x2, shrt, nullptr, M_, C_, C_);

    // --- ChannelMix path ---
    ln_kernel<<<M_, blk>>>(x2, ln2_w, ln2_b, gbuf);
    mix2_kernel<<<grid_elem, blk>>>(gbuf, fmix_k, fmix_r, gk, gr);
    gemm_nt<2><<<grid_gF, blk>>>(gk, fWk, kkb, nullptr, nullptr, M_, F_, C_);
    gemm_nt<0><<<grid_gC, blk>>>(kkb, fWv, kvb, nullptr, nullptr, M_, C_, F_);
    gemm_nt<4><<<grid_gC, blk>>>(gr, fWr, out, x2, kvb, M_, C_, C_);
}

// round 2
// speedup vs baseline: 2.5681x; 2.5681x over previous
#include <cuda_runtime.h>
#include <math.h>
#include <stdint.h>

// Problem dims (fixed by the reference)
#define B_ 8
#define T_ 2048
#define C_ 1024
#define F_ 4096
#define M_ (B_ * T_)   // 16384 rows

constexpr size_t S_  = (size_t)M_ * C_;   // 16,777,216
constexpr size_t SF_ = (size_t)M_ * F_;   // 67,108,864
constexpr size_t CC_ = (size_t)C_ * C_;
constexpr size_t FC_ = (size_t)F_ * C_;

// ---------------------------------------------------------------------------
// Scratch (static device globals — allocation-free per harness rules)
// ---------------------------------------------------------------------------
__device__ float g_h[S_];
__device__ float g_xk[S_];
__device__ float g_xv[S_];
__device__ float g_xr[S_];
__device__ float g_k[S_];
__device__ float g_v[S_];
__device__ float g_r[S_];
__device__ float g_rwkv[S_];
__device__ float g_short[S_];
__device__ float g_x2[S_];
__device__ float g_g[S_];
__device__ float g_gk[S_];
__device__ float g_gr[S_];
__device__ float g_kv[S_];
__device__ float g_kk[SF_];
__device__ float g_xt[S_];      // tf32-rounded copy of x
// tf32-rounded weights
__device__ float g_wkt[CC_];
__device__ float g_wvt[CC_];
__device__ float g_wrt[CC_];
__device__ float g_wot[CC_];
__device__ float g_wst[CC_];
__device__ float g_fwrt[CC_];
__device__ float g_fwkt[FC_];
__device__ float g_fwvt[FC_];

// ---------------------------------------------------------------------------
// tf32 helpers
// ---------------------------------------------------------------------------
__device__ __forceinline__ uint32_t f2tf32(float f) {
    uint32_t u;
    asm("cvt.rna.tf32.f32 %0, %1;" : "=r"(u) : "f"(f));
    return u;
}
__device__ __forceinline__ float f2tf32f(float f) {
    return __uint_as_float(f2tf32(f));
}

__device__ __forceinline__ void cp_async16(void* smem, const void* gmem) {
    uint32_t s = (uint32_t)__cvta_generic_to_shared(smem);
    asm volatile("cp.async.cg.shared.global [%0], [%1], 16;" :: "r"(s), "l"(gmem));
}
#define CP_COMMIT() asm volatile("cp.async.commit_group;")
#define CP_WAIT0()  asm volatile("cp.async.wait_group 0;")

__device__ __forceinline__ void mma_tf32(float* d, const uint32_t* a, const uint32_t* b) {
    asm volatile(
        "mma.sync.aligned.m16n8k8.row.col.f32.tf32.tf32.f32 "
        "{%0,%1,%2,%3}, {%4,%5,%6,%7}, {%8,%9}, {%0,%1,%2,%3};"
        : "+f"(d[0]), "+f"(d[1]), "+f"(d[2]), "+f"(d[3])
        : "r"(a[0]), "r"(a[1]), "r"(a[2]), "r"(a[3]),
          "r"(b[0]), "r"(b[1]));
}

// ---------------------------------------------------------------------------
// tf32 copy-convert (for x and all weights)
// ---------------------------------------------------------------------------
__global__ void __launch_bounds__(256) cvt_kernel(const float* __restrict__ src,
                                                  float* __restrict__ dst,
                                                  int n4) {
    int i = blockIdx.x * blockDim.x + threadIdx.x;
    if (i >= n4) return;
    float4 v = ((const float4*)src)[i];
    float4 o;
    o.x = f2tf32f(v.x); o.y = f2tf32f(v.y);
    o.z = f2tf32f(v.z); o.w = f2tf32f(v.w);
    ((float4*)dst)[i] = o;
}

// ---------------------------------------------------------------------------
// LayerNorm over last dim (C=1024). 256 thr per row, one float4 per thread.
// ---------------------------------------------------------------------------
__global__ void __launch_bounds__(256) ln_kernel(const float* __restrict__ x,
                                                 const float* __restrict__ w,
                                                 const float* __restrict__ b,
                                                 float* __restrict__ out) {
    const size_t row = blockIdx.x;
    const float4* xr = (const float4*)(x + row * C_);
    const int tid = threadIdx.x;

    float4 xv = xr[tid];
    float s  = xv.x + xv.y + xv.z + xv.w;
    float ss = xv.x * xv.x + xv.y * xv.y + xv.z * xv.z + xv.w * xv.w;

    #pragma unroll
    for (int o = 16; o > 0; o >>= 1) {
        s  += __shfl_down_sync(0xffffffffu, s,  o);
        ss += __shfl_down_sync(0xffffffffu, ss, o);
    }
    __shared__ float sm_s[8], sm_ss[8];
    int wid = tid >> 5, lid = tid & 31;
    if (lid == 0) { sm_s[wid] = s; sm_ss[wid] = ss; }
    __syncthreads();
    if (wid == 0) {
        s  = (lid < 8) ? sm_s[lid]  : 0.f;
        ss = (lid < 8) ? sm_ss[lid] : 0.f;
        #pragma unroll
        for (int o = 4; o > 0; o >>= 1) {
            s  += __shfl_down_sync(0xffffffffu, s,  o);
            ss += __shfl_down_sync(0xffffffffu, ss, o);
        }
        if (lid == 0) { sm_s[0] = s; sm_ss[0] = ss; }
    }
    __syncthreads();
    const float mean = sm_s[0] * (1.0f / C_);
    const float var  = sm_ss[0] * (1.0f / C_) - mean * mean;
    const float rstd = rsqrtf(var + 1e-5f);

    float4 wv = ((const float4*)w)[tid];
    float4 bv = ((const float4*)b)[tid];
    float4 ov;
    ov.x = (xv.x - mean) * rstd * wv.x + bv.x;
    ov.y = (xv.y - mean) * rstd * wv.y + bv.y;
    ov.z = (xv.z - mean) * rstd * wv.z + bv.z;
    ov.w = (xv.w - mean) * rstd * wv.w + bv.w;
    ((float4*)(out + row * C_))[tid] = ov;
}

// ---------------------------------------------------------------------------
// Time-shift + mix; outputs are tf32-rounded (GEMM inputs).
// ---------------------------------------------------------------------------
__global__ void __launch_bounds__(256) mix3_kernel(const float* __restrict__ h,
                                                   const float* __restrict__ mk,
                                                   const float* __restrict__ mv,
                                                   const float* __restrict__ mr,
                                                   float* __restrict__ xk,
                                                   float* __restrict__ xv,
                                                   float* __restrict__ xr) {
    size_t idx = (size_t)blockIdx.x * blockDim.x + threadIdx.x;
    if (idx >= S_) return;
    const int c = (int)(idx & (C_ - 1));
    const size_t row = idx >> 10;
    const int t = (int)(row & (T_ - 1));
    float hc = h[idx];
    float hh = (t == 0) ? 0.f : h[idx - C_];
    float a;
    a = mk[c]; xk[idx] = f2tf32f(hc * a + hh * (1.f - a));
    a = mv[c]; xv[idx] = f2tf32f(hc * a + hh * (1.f - a));
    a = mr[c]; xr[idx] = f2tf32f(hc * a + hh * (1.f - a));
}

__global__ void __launch_bounds__(256) mix2_kernel(const float* __restrict__ h,
                                                   const float* __restrict__ mk,
                                                   const float* __restrict__ mr,
                                                   float* __restrict__ xk,
                                                   float* __restrict__ xr) {
    size_t idx = (size_t)blockIdx.x * blockDim.x + threadIdx.x;
    if (idx >= S_) return;
    const int c = (int)(idx & (C_ - 1));
    const size_t row = idx >> 10;
    const int t = (int)(row & (T_ - 1));
    float hc = h[idx];
    float hh = (t == 0) ? 0.f : h[idx - C_];
    float a;
    a = mk[c]; xk[idx] = f2tf32f(hc * a + hh * (1.f - a));
    a = mr[c]; xr[idx] = f2tf32f(hc * a + hh * (1.f - a));
}

// ---------------------------------------------------------------------------
// WKV recurrence: one thread per (b, c). Fuses sigmoid-gate multiply and
// tf32 rounding (output feeds Wo GEMM only).
// ---------------------------------------------------------------------------
__global__ void __launch_bounds__(256) wkv_kernel(const float* __restrict__ decay,
                                                  const float* __restrict__ first,
                                                  const float* __restrict__ k,
                                                  const float* __restrict__ v,
                                                  const float* __restrict__ r,
                                                  float* __restrict__ out) {
    int gid = blockIdx.x * blockDim.x + threadIdx.x;
    if (gid >= B_ * C_) return;
    const int b = gid / C_;
    const int c = gid - b * C_;
    const float w = -__expf(decay[c]);
    const float u = first[c];
    size_t off = (size_t)b * T_ * C_ + c;

    float a = 0.f, bb = 0.f, p = -1e30f;
    for (int t = 0; t < T_; ++t, off += C_) {
        const float kt = k[off];
        const float vt = v[off];
        const float ww = u + kt;
        const float q  = fmaxf(p, ww);
        const float e1 = __expf(p - q);
        const float e2 = __expf(ww - q);
        const float y  = (e1 * a + e2 * vt) / (e1 * bb + e2);
        out[off] = f2tf32f(y * r[off]);
        const float ww2 = p + w;
        const float q2  = fmaxf(ww2, kt);
        const float f1  = __expf(ww2 - q2);
        const float f2  = __expf(kt - q2);
        a  = f1 * a + f2 * vt;
        bb = f1 * bb + f2;
        p  = q2;
    }
}

// ---------------------------------------------------------------------------
// tf32 tensor-core GEMM:  C[M,N] = A[M,K] * W[N,K]^T
// 128x128 tile, BK=16, 256 threads (8 warps @ 64x32), cp.async double buffer.
// Inputs must already be tf32-rounded. MODE epilogues as before:
//   0 = store, 1 = sigmoid, 2 = relu^2 (+tf32 round), 3 = +aux1,
//   4 = aux1 + sigmoid(acc)*aux2
// ---------------------------------------------------------------------------
#define BM 128
#define BN 128
#define BK 16
#define BKP 20   // padded k-stride (floats): conflict-free frag loads + 16B aligned

template <int MODE>
__global__ void __launch_bounds__(256) gemm_tc(const float* __restrict__ A,
                                               const float* __restrict__ W,
                                               float* __restrict__ Cc,
                                               const float* __restrict__ aux1,
                                               const float* __restrict__ aux2,
                                               int M, int N, int K) {
    __shared__ __align__(16) uint32_t As[2][BM][BKP];
    __shared__ __align__(16) uint32_t Bs[2][BN][BKP];

    const int tid  = threadIdx.x;
    const int wid  = tid >> 5;
    const int lane = tid & 31;
    const int g    = lane >> 2;   // groupID (0..7)
    const int tig  = lane & 3;    // thread-in-group (0..3)

    const int warp_m = wid >> 2;  // 0..1 -> 64 rows
    const int warp_n = wid & 3;   // 0..3 -> 32 cols

    const size_t brow = blockIdx.y;
    const size_t bcol = blockIdx.x;

    // global->smem mapping: thread handles 2 rows (lrow, lrow+64), one 16B k-chunk
    const int lrow = tid >> 2;        // 0..63
    const int lk   = (tid & 3) * 4;   // 0,4,8,12

    const float* Ag = A + (brow * BM + lrow) * (size_t)K + lk;
    const float* Wg = W + (bcol * BN + lrow) * (size_t)K + lk;

    float acc[4][4][4];
    #pragma unroll
    for (int i = 0; i < 4; ++i)
        #pragma unroll
        for (int j = 0; j < 4; ++j)
            #pragma unroll
            for (int r = 0; r < 4; ++r) acc[i][j][r] = 0.f;

    auto load_stage = [&](int s, int k0) {
        cp_async16(&As[s][lrow][lk],      Ag + k0);
        cp_async16(&As[s][lrow + 64][lk], Ag + 64 * (size_t)K + k0);
        cp_async16(&Bs[s][lrow][lk],      Wg + k0);
        cp_async16(&Bs[s][lrow + 64][lk], Wg + 64 * (size_t)K + k0);
    };

    load_stage(0, 0);
    CP_COMMIT();
    CP_WAIT0();
    __syncthreads();

    const int nk = K / BK;
    for (int it = 0; it < nk; ++it) {
        const int cur = it & 1;
        if (it + 1 < nk) {
            load_stage(cur ^ 1, (it + 1) * BK);
            CP_COMMIT();
        }

        #pragma unroll
        for (int ks = 0; ks < 2; ++ks) {
            const int kb = ks * 8;
            uint32_t af[4][4];
            uint32_t bf[4][2];
            #pragma unroll
            for (int mt = 0; mt < 4; ++mt) {
                const int row = warp_m * 64 + mt * 16;
                af[mt][0] = As[cur][row + g    ][kb + tig];
                af[mt][1] = As[cur][row + g + 8][kb + tig];
                af[mt][2] = As[cur][row + g    ][kb + tig + 4];
                af[mt][3] = As[cur][row + g + 8][kb + tig + 4];
            }
            #pragma unroll
            for (int nt = 0; nt < 4; ++nt) {
                const int col = warp_n * 32 + nt * 8;
                bf[nt][0] = Bs[cur][col + g][kb + tig];
                bf[nt][1] = Bs[cur][col + g][kb + tig + 4];
            }
            #pragma unroll
            for (int mt = 0; mt < 4; ++mt)
                #pragma unroll
                for (int nt = 0; nt < 4; ++nt)
                    mma_tf32(acc[mt][nt], af[mt], bf[nt]);
        }

        if (it + 1 < nk) {
            CP_WAIT0();
            __syncthreads();
        }
    }

    // Epilogue
    #pragma unroll
    for (int mt = 0; mt < 4; ++mt) {
        const int r0 = (int)(brow * BM) + warp_m * 64 + mt * 16 + g;
        #pragma unroll
        for (int nt = 0; nt < 4; ++nt) {
            const int c0 = (int)(bcol * BN) + warp_n * 32 + nt * 8 + 2 * tig;
            #pragma unroll
            for (int half = 0; half < 2; ++half) {
                const int row = r0 + half * 8;
                const size_t off = (size_t)row * N + c0;
                float v0 = acc[mt][nt][half * 2 + 0];
                float v1 = acc[mt][nt][half * 2 + 1];
                if (MODE == 1) {
                    v0 = 1.f / (1.f + __expf(-v0));
                    v1 = 1.f / (1.f + __expf(-v1));
                } else if (MODE == 2) {
                    v0 = fmaxf(v0, 0.f); v0 = f2tf32f(v0 * v0);
                    v1 = fmaxf(v1, 0.f); v1 = f2tf32f(v1 * v1);
                } else if (MODE == 3) {
                    float2 a1 = *(const float2*)(aux1 + off);
                    v0 += a1.x; v1 += a1.y;
                } else if (MODE == 4) {
                    float2 a1 = *(const float2*)(aux1 + off);
                    float2 a2 = *(const float2*)(aux2 + off);
                    v0 = a1.x + (1.f / (1.f + __expf(-v0))) * a2.x;
                    v1 = a1.y + (1.f / (1.f + __expf(-v1))) * a2.y;
                }
                float2 o; o.x = v0; o.y = v1;
                *(float2*)(Cc + off) = o;
            }
        }
    }
}

// ---------------------------------------------------------------------------
// Launch
// ---------------------------------------------------------------------------
static float* sym(const void* s) {
    void* p = nullptr;
    cudaGetSymbolAddress(&p, s);
    return (float*)p;
}

extern "C" void kernel_launch(void* const* d_in, const int* in_sizes, int n_in,
                              void* d_out, int out_size) {
    const float* x        = (const float*)d_in[0];
    const float* ln1_w    = (const float*)d_in[1];
    const float* ln1_b    = (const float*)d_in[2];
    const float* ln2_w    = (const float*)d_in[3];
    const float* ln2_b    = (const float*)d_in[4];
    const float* t_decay  = (const float*)d_in[5];
    const float* t_first  = (const float*)d_in[6];
    const float* mix_k    = (const float*)d_in[7];
    const float* mix_v    = (const float*)d_in[8];
    const float* mix_r    = (const float*)d_in[9];
    const float* Wk       = (const float*)d_in[10];
    const float* Wv       = (const float*)d_in[11];
    const float* Wr       = (const float*)d_in[12];
    const float* Wo       = (const float*)d_in[13];
    const float* fmix_k   = (const float*)d_in[14];
    const float* fmix_r   = (const float*)d_in[15];
    const float* fWk      = (const float*)d_in[16];   // [F, C]
    const float* fWr      = (const float*)d_in[17];   // [C, C]
    const float* fWv      = (const float*)d_in[18];   // [C, F]
    const float* shortW   = (const float*)d_in[19];
    float* out = (float*)d_out;

    float* h    = sym(g_h);
    float* xk   = sym(g_xk);
    float* xv   = sym(g_xv);
    float* xr   = sym(g_xr);
    float* kbuf = sym(g_k);
    float* vbuf = sym(g_v);
    float* rbuf = sym(g_r);
    float* rwkv = sym(g_rwkv);
    float* shrt = sym(g_short);
    float* x2   = sym(g_x2);
    float* gbuf = sym(g_g);
    float* gk   = sym(g_gk);
    float* gr   = sym(g_gr);
    float* kvb  = sym(g_kv);
    float* kkb  = sym(g_kk);
    float* xt   = sym(g_xt);
    float* wkt  = sym(g_wkt);
    float* wvt  = sym(g_wvt);
    float* wrt  = sym(g_wrt);
    float* wot  = sym(g_wot);
    float* wst  = sym(g_wst);
    float* fwrt = sym(g_fwrt);
    float* fwkt = sym(g_fwkt);
    float* fwvt = sym(g_fwvt);

    const dim3 blk(256);
    const dim3 grid_elem((unsigned)((S_ + 255) / 256));
    const dim3 grid_gC(C_ / BN, M_ / BM);   // N=1024
    const dim3 grid_gF(F_ / BN, M_ / BM);   // N=4096

    // --- tf32 pre-conversion (weights + x) ---
    const int nCC4 = (int)(CC_ / 4), nFC4 = (int)(FC_ / 4), nS4 = (int)(S_ / 4);
    cvt_kernel<<<(nS4 + 255) / 256, blk>>>(x, xt, nS4);
    cvt_kernel<<<(nCC4 + 255) / 256, blk>>>(Wk, wkt, nCC4);
    cvt_kernel<<<(nCC4 + 255) / 256, blk>>>(Wv, wvt, nCC4);
    cvt_kernel<<<(nCC4 + 255) / 256, blk>>>(Wr, wrt, nCC4);
    cvt_kernel<<<(nCC4 + 255) / 256, blk>>>(Wo, wot, nCC4);
    cvt_kernel<<<(nCC4 + 255) / 256, blk>>>(shortW, wst, nCC4);
    cvt_kernel<<<(nCC4 + 255) / 256, blk>>>(fWr, fwrt, nCC4);
    cvt_kernel<<<(nFC4 + 255) / 256, blk>>>(fWk, fwkt, nFC4);
    cvt_kernel<<<(nFC4 + 255) / 256, blk>>>(fWv, fwvt, nFC4);

    // --- TimeMix path ---
    ln_kernel<<<M_, blk>>>(x, ln1_w, ln1_b, h);
    mix3_kernel<<<grid_elem, blk>>>(h, mix_k, mix_v, mix_r, xk, xv, xr);
    gemm_tc<0><<<grid_gC, blk>>>(xk, wkt, kbuf, nullptr, nullptr, M_, C_, C_);
    gemm_tc<0><<<grid_gC, blk>>>(xv, wvt, vbuf, nullptr, nullptr, M_, C_, C_);
    gemm_tc<1><<<grid_gC, blk>>>(xr, wrt, rbuf, nullptr, nullptr, M_, C_, C_);
    wkv_kernel<<<(B_ * C_) / 256, blk>>>(t_decay, t_first, kbuf, vbuf, rbuf, rwkv);
    gemm_tc<0><<<grid_gC, blk>>>(xt, wst, shrt, nullptr, nullptr, M_, C_, C_);
    gemm_tc<3><<<grid_gC, blk>>>(rwkv, wot, x2, shrt, nullptr, M_, C_, C_);

    // --- ChannelMix path ---
    ln_kernel<<<M_, blk>>>(x2, ln2_w, ln2_b, gbuf);
    mix2_kernel<<<grid_elem, blk>>>(gbuf, fmix_k, fmix_r, gk, gr);
    gemm_tc<2><<<grid_gF, blk>>>(gk, fwkt, kkb, nullptr, nullptr, M_, F_, C_);
    gemm_tc<0><<<grid_gC, blk>>>(kkb, fwvt, kvb, nullptr, nullptr, M_, C_, F_);
    gemm_tc<4><<<grid_gC, blk>>>(gr, fwrt, out, x2, kvb, M_, C_, C_);
}

// round 4
// speedup vs baseline: 4.0157x; 1.5637x over previous
#include <cuda_runtime.h>
#include <math.h>
#include <stdint.h>

// Problem dims (fixed by the reference)
#define B_ 8
#define T_ 2048
#define C_ 1024
#define F_ 4096
#define M_ (B_ * T_)   // 16384 rows

constexpr size_t S_  = (size_t)M_ * C_;   // 16,777,216
constexpr size_t SF_ = (size_t)M_ * F_;   // 67,108,864
constexpr size_t CC_ = (size_t)C_ * C_;
constexpr size_t FC_ = (size_t)F_ * C_;

#define NCH 16            // WKV chunks
#define CHL (T_ / NCH)    // 128 steps per chunk
#define NCHAN (B_ * C_)   // 8192 channels

// ---------------------------------------------------------------------------
// Scratch (static device globals — allocation-free per harness rules)
// ---------------------------------------------------------------------------
__device__ float g_h[S_];
__device__ float g_xk[S_];
__device__ float g_xv[S_];
__device__ float g_xr[S_];
__device__ float g_k[S_];
__device__ float g_v[S_];
__device__ float g_r[S_];
__device__ float g_rwkv[S_];
__device__ float g_short[S_];
__device__ float g_x2[S_];
__device__ float g_g[S_];
__device__ float g_gk[S_];
__device__ float g_gr[S_];
__device__ float g_kv[S_];
__device__ float g_kk[SF_];
__device__ float g_xt[S_];      // tf32-rounded copy of x
// tf32-rounded weights
__device__ float g_wkt[CC_];
__device__ float g_wvt[CC_];
__device__ float g_wrt[CC_];
__device__ float g_wot[CC_];
__device__ float g_wst[CC_];
__device__ float g_fwrt[CC_];
__device__ float g_fwkt[FC_];
__device__ float g_fwvt[FC_];
// WKV chunk-scan state
__device__ float g_sa[NCHAN * NCH], g_sbv[NCHAN * NCH], g_sp[NCHAN * NCH];
__device__ float g_pa[NCHAN * NCH], g_pbv[NCHAN * NCH], g_pp[NCHAN * NCH];

// ---------------------------------------------------------------------------
// helpers
// ---------------------------------------------------------------------------
__device__ __forceinline__ uint32_t f2tf32(float f) {
    uint32_t u;
    asm("cvt.rna.tf32.f32 %0, %1;" : "=r"(u) : "f"(f));
    return u;
}
__device__ __forceinline__ float f2tf32f(float f) {
    return __uint_as_float(f2tf32(f));
}

__device__ __forceinline__ void cp_async16(void* smem, const void* gmem) {
    uint32_t s = (uint32_t)__cvta_generic_to_shared(smem);
    asm volatile("cp.async.cg.shared.global [%0], [%1], 16;" :: "r"(s), "l"(gmem));
}
#define CP_COMMIT() asm volatile("cp.async.commit_group;")
#define CP_WAIT0()  asm volatile("cp.async.wait_group 0;")
#define CP_WAIT1()  asm volatile("cp.async.wait_group 1;")

__device__ __forceinline__ void mma_tf32(float* d, const uint32_t* a, const uint32_t* b) {
    asm volatile(
        "mma.sync.aligned.m16n8k8.row.col.f32.tf32.tf32.f32 "
        "{%0,%1,%2,%3}, {%4,%5,%6,%7}, {%8,%9}, {%0,%1,%2,%3};"
        : "+f"(d[0]), "+f"(d[1]), "+f"(d[2]), "+f"(d[3])
        : "r"(a[0]), "r"(a[1]), "r"(a[2]), "r"(a[3]),
          "r"(b[0]), "r"(b[1]));
}

// ---------------------------------------------------------------------------
// tf32 copy-convert (for x and all weights)
// ---------------------------------------------------------------------------
__global__ void __launch_bounds__(256) cvt_kernel(const float* __restrict__ src,
                                                  float* __restrict__ dst,
                                                  int n4) {
    int i = blockIdx.x * blockDim.x + threadIdx.x;
    if (i >= n4) return;
    float4 v = ((const float4*)src)[i];
    float4 o;
    o.x = f2tf32f(v.x); o.y = f2tf32f(v.y);
    o.z = f2tf32f(v.z); o.w = f2tf32f(v.w);
    ((float4*)dst)[i] = o;
}

// ---------------------------------------------------------------------------
// LayerNorm over last dim (C=1024). 256 thr per row, one float4 per thread.
// ---------------------------------------------------------------------------
__global__ void __launch_bounds__(256) ln_kernel(const float* __restrict__ x,
                                                 const float* __restrict__ w,
                                                 const float* __restrict__ b,
                                                 float* __restrict__ out) {
    const size_t row = blockIdx.x;
    const float4* xr = (const float4*)(x + row * C_);
    const int tid = threadIdx.x;

    float4 xv = xr[tid];
    float s  = xv.x + xv.y + xv.z + xv.w;
    float ss = xv.x * xv.x + xv.y * xv.y + xv.z * xv.z + xv.w * xv.w;

    #pragma unroll
    for (int o = 16; o > 0; o >>= 1) {
        s  += __shfl_down_sync(0xffffffffu, s,  o);
        ss += __shfl_down_sync(0xffffffffu, ss, o);
    }
    __shared__ float sm_s[8], sm_ss[8];
    int wid = tid >> 5, lid = tid & 31;
    if (lid == 0) { sm_s[wid] = s; sm_ss[wid] = ss; }
    __syncthreads();
    if (wid == 0) {
        s  = (lid < 8) ? sm_s[lid]  : 0.f;
        ss = (lid < 8) ? sm_ss[lid] : 0.f;
        #pragma unroll
        for (int o = 4; o > 0; o >>= 1) {
            s  += __shfl_down_sync(0xffffffffu, s,  o);
            ss += __shfl_down_sync(0xffffffffu, ss, o);
        }
        if (lid == 0) { sm_s[0] = s; sm_ss[0] = ss; }
    }
    __syncthreads();
    const float mean = sm_s[0] * (1.0f / C_);
    const float var  = sm_ss[0] * (1.0f / C_) - mean * mean;
    const float rstd = rsqrtf(var + 1e-5f);

    float4 wv = ((const float4*)w)[tid];
    float4 bv = ((const float4*)b)[tid];
    float4 ov;
    ov.x = (xv.x - mean) * rstd * wv.x + bv.x;
    ov.y = (xv.y - mean) * rstd * wv.y + bv.y;
    ov.z = (xv.z - mean) * rstd * wv.z + bv.z;
    ov.w = (xv.w - mean) * rstd * wv.w + bv.w;
    ((float4*)(out + row * C_))[tid] = ov;
}

// ---------------------------------------------------------------------------
// Time-shift + mix; outputs tf32-rounded (GEMM inputs)
// ---------------------------------------------------------------------------
__global__ void __launch_bounds__(256) mix3_kernel(const float* __restrict__ h,
                                                   const float* __restrict__ mk,
                                                   const float* __restrict__ mv,
                                                   const float* __restrict__ mr,
                                                   float* __restrict__ xk,
                                                   float* __restrict__ xv,
                                                   float* __restrict__ xr) {
    size_t idx = (size_t)blockIdx.x * blockDim.x + threadIdx.x;
    if (idx >= S_) return;
    const int c = (int)(idx & (C_ - 1));
    const size_t row = idx >> 10;
    const int t = (int)(row & (T_ - 1));
    float hc = h[idx];
    float hh = (t == 0) ? 0.f : h[idx - C_];
    float a;
    a = mk[c]; xk[idx] = f2tf32f(hc * a + hh * (1.f - a));
    a = mv[c]; xv[idx] = f2tf32f(hc * a + hh * (1.f - a));
    a = mr[c]; xr[idx] = f2tf32f(hc * a + hh * (1.f - a));
}

__global__ void __launch_bounds__(256) mix2_kernel(const float* __restrict__ h,
                                                   const float* __restrict__ mk,
                                                   const float* __restrict__ mr,
                                                   float* __restrict__ xk,
                                                   float* __restrict__ xr) {
    size_t idx = (size_t)blockIdx.x * blockDim.x + threadIdx.x;
    if (idx >= S_) return;
    const int c = (int)(idx & (C_ - 1));
    const size_t row = idx >> 10;
    const int t = (int)(row & (T_ - 1));
    float hc = h[idx];
    float hh = (t == 0) ? 0.f : h[idx - C_];
    float a;
    a = mk[c]; xk[idx] = f2tf32f(hc * a + hh * (1.f - a));
    a = mr[c]; xr[idx] = f2tf32f(hc * a + hh * (1.f - a));
}

// ---------------------------------------------------------------------------
// WKV chunk-parallel scan (3 passes).
// Unnormalized recurrence: A_t = e^w A_{t-1} + e^{k_t} v_t per channel, with
// state (a, b, p) meaning A = a*e^p, B = b*e^p. Associative across chunks.
// ---------------------------------------------------------------------------
__global__ void __launch_bounds__(256) wkv_part(const float* __restrict__ decay,
                                                const float* __restrict__ k,
                                                const float* __restrict__ v) {
    int gid = blockIdx.x * blockDim.x + threadIdx.x;  // 131072
    int j    = gid >> 13;          // chunk 0..15
    int chan = gid & (NCHAN - 1);  // 0..8191
    int b = chan >> 10;
    int c = chan & (C_ - 1);
    const float w = -__expf(decay[c]);
    size_t off = ((size_t)b * T_ + (size_t)j * CHL) * C_ + c;

    float a = 0.f, bb = 0.f, p = -1e30f;
    #pragma unroll 4
    for (int t = 0; t < CHL; ++t, off += C_) {
        const float kt = k[off];
        const float vt = v[off];
        const float ww2 = p + w;
        const float q2  = fmaxf(ww2, kt);
        const float f1  = __expf(ww2 - q2);
        const float f2  = __expf(kt - q2);
        a  = f1 * a + f2 * vt;
        bb = f1 * bb + f2;
        p  = q2;
    }
    g_sa[j * NCHAN + chan]  = a;
    g_sbv[j * NCHAN + chan] = bb;
    g_sp[j * NCHAN + chan]  = p;
}

__global__ void __launch_bounds__(256) wkv_scan(const float* __restrict__ decay) {
    int chan = blockIdx.x * blockDim.x + threadIdx.x;  // 8192
    if (chan >= NCHAN) return;
    int c = chan & (C_ - 1);
    const float w = -__expf(decay[c]);
    const float Lw = (float)CHL * w;

    float a = 0.f, bb = 0.f, p = -1e30f;
    #pragma unroll
    for (int j = 0; j < NCH; ++j) {
        g_pa[j * NCHAN + chan]  = a;
        g_pbv[j * NCHAN + chan] = bb;
        g_pp[j * NCHAN + chan]  = p;
        const float ca = g_sa[j * NCHAN + chan];
        const float cb = g_sbv[j * NCHAN + chan];
        const float cp = g_sp[j * NCHAN + chan];
        const float pw = p + Lw;
        const float q  = fmaxf(pw, cp);
        const float e0 = __expf(pw - q);
        const float e1 = __expf(cp - q);
        a  = a * e0 + ca * e1;
        bb = bb * e0 + cb * e1;
        p  = q;
    }
}

__global__ void __launch_bounds__(256) wkv_out(const float* __restrict__ decay,
                                               const float* __restrict__ first,
                                               const float* __restrict__ k,
                                               const float* __restrict__ v,
                                               const float* __restrict__ r,
                                               float* __restrict__ out) {
    int gid = blockIdx.x * blockDim.x + threadIdx.x;
    int j    = gid >> 13;
    int chan = gid & (NCHAN - 1);
    int b = chan >> 10;
    int c = chan & (C_ - 1);
    const float w = -__expf(decay[c]);
    const float u = first[c];
    size_t off = ((size_t)b * T_ + (size_t)j * CHL) * C_ + c;

    float a  = g_pa[j * NCHAN + chan];
    float bb = g_pbv[j * NCHAN + chan];
    float p  = g_pp[j * NCHAN + chan];

    #pragma unroll 4
    for (int t = 0; t < CHL; ++t, off += C_) {
        const float kt = k[off];
        const float vt = v[off];
        const float ww = u + kt;
        const float q  = fmaxf(p, ww);
        const float e1 = __expf(p - q);
        const float e2 = __expf(ww - q);
        const float y  = (e1 * a + e2 * vt) / (e1 * bb + e2);
        out[off] = f2tf32f(y * r[off]);
        const float ww2 = p + w;
        const float q2  = fmaxf(ww2, kt);
        const float f1  = __expf(ww2 - q2);
        const float f2  = __expf(kt - q2);
        a  = f1 * a + f2 * vt;
        bb = f1 * bb + f2;
        p  = q2;
    }
}

// ---------------------------------------------------------------------------
// tf32 tensor-core GEMM:  C[M,N] = A[M,K] * W[N,K]^T
// 128x128 tile, BK=16, 256 threads (8 warps @ 64x32), 3-stage cp.async
// pipeline, 2 CTAs/SM. Inputs must already be tf32-rounded.
// MODE: 0 = store, 1 = sigmoid, 2 = relu^2 (+tf32 round), 3 = +aux1,
//       4 = aux1 + sigmoid(acc)*aux2
// ---------------------------------------------------------------------------
#define BM 128
#define BN 128
#define BK 16
#define BKP 20   // padded k-stride (floats): conflict-free frag loads, 16B aligned
#define STG 3
#define STAGE_FLTS (128 * BKP)
#define GEMM_SMEM (STG * STAGE_FLTS * 2 * 4)   // 61440 bytes

template <int MODE>
__global__ void __launch_bounds__(256, 2) gemm_tc(const float* __restrict__ A,
                                                  const float* __restrict__ W,
                                                  float* __restrict__ Cc,
                                                  const float* __restrict__ aux1,
                                                  const float* __restrict__ aux2,
                                                  int N, int K) {
    extern __shared__ float sm[];
    float* AsBase = sm;                      // [STG][128][BKP]
    float* BsBase = sm + STG * STAGE_FLTS;   // [STG][128][BKP]

    const int tid  = threadIdx.x;
    const int wid  = tid >> 5;
    const int lane = tid & 31;
    const int g    = lane >> 2;   // 0..7
    const int tig  = lane & 3;    // 0..3

    const int warp_m = wid >> 2;  // 0..1 -> 64 rows
    const int warp_n = wid & 3;   // 0..3 -> 32 cols

    const size_t brow = blockIdx.y;
    const size_t bcol = blockIdx.x;

    const int lrow = tid >> 2;        // 0..63
    const int lk   = (tid & 3) * 4;   // 0,4,8,12

    const float* Ag = A + (brow * BM + lrow) * (size_t)K + lk;
    const float* Wg = W + (bcol * BN + lrow) * (size_t)K + lk;

    float acc[4][4][4];
    #pragma unroll
    for (int i = 0; i < 4; ++i)
        #pragma unroll
        for (int j = 0; j < 4; ++j)
            #pragma unroll
            for (int r = 0; r < 4; ++r) acc[i][j][r] = 0.f;

    auto load_stage = [&](int s, int k0) {
        float* a = AsBase + s * STAGE_FLTS;
        float* b = BsBase + s * STAGE_FLTS;
        cp_async16(&a[lrow * BKP + lk],        Ag + k0);
        cp_async16(&a[(lrow + 64) * BKP + lk], Ag + 64 * (size_t)K + k0);
        cp_async16(&b[lrow * BKP + lk],        Wg + k0);
        cp_async16(&b[(lrow + 64) * BKP + lk], Wg + 64 * (size_t)K + k0);
    };

    load_stage(0, 0); CP_COMMIT();
    load_stage(1, BK); CP_COMMIT();

    const int nk = K / BK;
    for (int it = 0; it < nk; ++it) {
        const int cur = it % 3;
        if (it == nk - 1) { CP_WAIT0(); } else { CP_WAIT1(); }
        __syncthreads();

        const uint32_t* As = (const uint32_t*)(AsBase + cur * STAGE_FLTS);
        const uint32_t* Bs = (const uint32_t*)(BsBase + cur * STAGE_FLTS);

        #pragma unroll
        for (int ks = 0; ks < 2; ++ks) {
            const int kb = ks * 8;
            uint32_t af[4][4];
            uint32_t bf[4][2];
            #pragma unroll
            for (int mt = 0; mt < 4; ++mt) {
                const int row = warp_m * 64 + mt * 16;
                af[mt][0] = As[(row + g    ) * BKP + kb + tig];
                af[mt][1] = As[(row + g + 8) * BKP + kb + tig];
                af[mt][2] = As[(row + g    ) * BKP + kb + tig + 4];
                af[mt][3] = As[(row + g + 8) * BKP + kb + tig + 4];
            }
            #pragma unroll
            for (int nt = 0; nt < 4; ++nt) {
                const int col = warp_n * 32 + nt * 8;
                bf[nt][0] = Bs[(col + g) * BKP + kb + tig];
                bf[nt][1] = Bs[(col + g) * BKP + kb + tig + 4];
            }
            #pragma unroll
            for (int mt = 0; mt < 4; ++mt)
                #pragma unroll
                for (int nt = 0; nt < 4; ++nt)
                    mma_tf32(acc[mt][nt], af[mt], bf[nt]);
        }

        if (it + 2 < nk) {
            load_stage((it + 2) % 3, (it + 2) * BK);
            CP_COMMIT();
        }
    }

    // Epilogue
    #pragma unroll
    for (int mt = 0; mt < 4; ++mt) {
        const int r0 = (int)(brow * BM) + warp_m * 64 + mt * 16 + g;
        #pragma unroll
        for (int nt = 0; nt < 4; ++nt) {
            const int c0 = (int)(bcol * BN) + warp_n * 32 + nt * 8 + 2 * tig;
            #pragma unroll
            for (int half = 0; half < 2; ++half) {
                const int row = r0 + half * 8;
                const size_t off = (size_t)row * N + c0;
                float v0 = acc[mt][nt][half * 2 + 0];
                float v1 = acc[mt][nt][half * 2 + 1];
                if (MODE == 1) {
                    v0 = 1.f / (1.f + __expf(-v0));
                    v1 = 1.f / (1.f + __expf(-v1));
                } else if (MODE == 2) {
                    v0 = fmaxf(v0, 0.f); v0 = f2tf32f(v0 * v0);
                    v1 = fmaxf(v1, 0.f); v1 = f2tf32f(v1 * v1);
                } else if (MODE == 3) {
                    float2 a1 = *(const float2*)(aux1 + off);
                    v0 += a1.x; v1 += a1.y;
                } else if (MODE == 4) {
                    float2 a1 = *(const float2*)(aux1 + off);
                    float2 a2 = *(const float2*)(aux2 + off);
                    v0 = a1.x + (1.f / (1.f + __expf(-v0))) * a2.x;
                    v1 = a1.y + (1.f / (1.f + __expf(-v1))) * a2.y;
                }
                float2 o; o.x = v0; o.y = v1;
                *(float2*)(Cc + off) = o;
            }
        }
    }
}

// ---------------------------------------------------------------------------
// Launch
// ---------------------------------------------------------------------------
static float* sym(const void* s) {
    void* p = nullptr;
    cudaGetSymbolAddress(&p, s);
    return (float*)p;
}

extern "C" void kernel_launch(void* const* d_in, const int* in_sizes, int n_in,
                              void* d_out, int out_size) {
    const float* x        = (const float*)d_in[0];
    const float* ln1_w    = (const float*)d_in[1];
    const float* ln1_b    = (const float*)d_in[2];
    const float* ln2_w    = (const float*)d_in[3];
    const float* ln2_b    = (const float*)d_in[4];
    const float* t_decay  = (const float*)d_in[5];
    const float* t_first  = (const float*)d_in[6];
    const float* mix_k    = (const float*)d_in[7];
    const float* mix_v    = (const float*)d_in[8];
    const float* mix_r    = (const float*)d_in[9];
    const float* Wk       = (const float*)d_in[10];
    const float* Wv       = (const float*)d_in[11];
    const float* Wr       = (const float*)d_in[12];
    const float* Wo       = (const float*)d_in[13];
    const float* fmix_k   = (const float*)d_in[14];
    const float* fmix_r   = (const float*)d_in[15];
    const float* fWk      = (const float*)d_in[16];   // [F, C]
    const float* fWr      = (const float*)d_in[17];   // [C, C]
    const float* fWv      = (const float*)d_in[18];   // [C, F]
    const float* shortW   = (const float*)d_in[19];
    float* out = (float*)d_out;

    float* h    = sym(g_h);
    float* xk   = sym(g_xk);
    float* xv   = sym(g_xv);
    float* xr   = sym(g_xr);
    float* kbuf = sym(g_k);
    float* vbuf = sym(g_v);
    float* rbuf = sym(g_r);
    float* rwkv = sym(g_rwkv);
    float* shrt = sym(g_short);
    float* x2   = sym(g_x2);
    float* gbuf = sym(g_g);
    float* gk   = sym(g_gk);
    float* gr   = sym(g_gr);
    float* kvb  = sym(g_kv);
    float* kkb  = sym(g_kk);
    float* xt   = sym(g_xt);
    float* wkt  = sym(g_wkt);
    float* wvt  = sym(g_wvt);
    float* wrt  = sym(g_wrt);
    float* wot  = sym(g_wot);
    float* wst  = sym(g_wst);
    float* fwrt = sym(g_fwrt);
    float* fwkt = sym(g_fwkt);
    float* fwvt = sym(g_fwvt);

    cudaFuncSetAttribute(gemm_tc<0>, cudaFuncAttributeMaxDynamicSharedMemorySize, GEMM_SMEM);
    cudaFuncSetAttribute(gemm_tc<1>, cudaFuncAttributeMaxDynamicSharedMemorySize, GEMM_SMEM);
    cudaFuncSetAttribute(gemm_tc<2>, cudaFuncAttributeMaxDynamicSharedMemorySize, GEMM_SMEM);
    cudaFuncSetAttribute(gemm_tc<3>, cudaFuncAttributeMaxDynamicSharedMemorySize, GEMM_SMEM);
    cudaFuncSetAttribute(gemm_tc<4>, cudaFuncAttributeMaxDynamicSharedMemorySize, GEMM_SMEM);

    const dim3 blk(256);
    const dim3 grid_elem((unsigned)((S_ + 255) / 256));
    const dim3 grid_gC(C_ / BN, M_ / BM);   // (8, 128)
    const dim3 grid_gF(F_ / BN, M_ / BM);   // (32, 128)

    // --- tf32 pre-conversion (weights + x) ---
    const int nCC4 = (int)(CC_ / 4), nFC4 = (int)(FC_ / 4), nS4 = (int)(S_ / 4);
    cvt_kernel<<<(nS4 + 255) / 256, blk>>>(x, xt, nS4);
    cvt_kernel<<<(nCC4 + 255) / 256, blk>>>(Wk, wkt, nCC4);
    cvt_kernel<<<(nCC4 + 255) / 256, blk>>>(Wv, wvt, nCC4);
    cvt_kernel<<<(nCC4 + 255) / 256, blk>>>(Wr, wrt, nCC4);
    cvt_kernel<<<(nCC4 + 255) / 256, blk>>>(Wo, wot, nCC4);
    cvt_kernel<<<(nCC4 + 255) / 256, blk>>>(shortW, wst, nCC4);
    cvt_kernel<<<(nCC4 + 255) / 256, blk>>>(fWr, fwrt, nCC4);
    cvt_kernel<<<(nFC4 + 255) / 256, blk>>>(fWk, fwkt, nFC4);
    cvt_kernel<<<(nFC4 + 255) / 256, blk>>>(fWv, fwvt, nFC4);

    // --- TimeMix path ---
    ln_kernel<<<M_, blk>>>(x, ln1_w, ln1_b, h);
    mix3_kernel<<<grid_elem, blk>>>(h, mix_k, mix_v, mix_r, xk, xv, xr);
    gemm_tc<0><<<grid_gC, blk, GEMM_SMEM>>>(xk, wkt, kbuf, nullptr, nullptr, C_, C_);
    gemm_tc<0><<<grid_gC, blk, GEMM_SMEM>>>(xv, wvt, vbuf, nullptr, nullptr, C_, C_);
    gemm_tc<1><<<grid_gC, blk, GEMM_SMEM>>>(xr, wrt, rbuf, nullptr, nullptr, C_, C_);
    wkv_part<<<(NCHAN * NCH) / 256, blk>>>(t_decay, kbuf, vbuf);
    wkv_scan<<<NCHAN / 256, blk>>>(t_decay);
    wkv_out<<<(NCHAN * NCH) / 256, blk>>>(t_decay, t_first, kbuf, vbuf, rbuf, rwkv);
    gemm_tc<0><<<grid_gC, blk, GEMM_SMEM>>>(xt, wst, shrt, nullptr, nullptr, C_, C_);
    gemm_tc<3><<<grid_gC, blk, GEMM_SMEM>>>(rwkv, wot, x2, shrt, nullptr, C_, C_);

    // --- ChannelMix path ---
    ln_kernel<<<M_, blk>>>(x2, ln2_w, ln2_b, gbuf);
    mix2_kernel<<<grid_elem, blk>>>(gbuf, fmix_k, fmix_r, gk, gr);
    gemm_tc<2><<<grid_gF, blk, GEMM_SMEM>>>(gk, fwkt, kkb, nullptr, nullptr, F_, C_);
    gemm_tc<0><<<grid_gC, blk, GEMM_SMEM>>>(kkb, fwvt, kvb, nullptr, nullptr, C_, F_);
    gemm_tc<4><<<grid_gC, blk, GEMM_SMEM>>>(gr, fwrt, out, x2, kvb, C_, C_);
}